// round 3
// baseline (speedup 1.0000x reference)
#include <cuda_runtime.h>
#include <cstdint>

// BondPredictor: out[b,c,i,j] = mask ? (gelu(pair@W1+b1)@W2+b2)[c] : -10000
// Factorization: pair@W1 = S_i + S_j + |a_i-a_j|@W1b, with S = A@W1a + 0.5*b1.

#define D 512
#define NA 256
#define B_SZ 2
#define T_SEQ 1024
#define NB 7
#define MASK_FILL -10000.0f

// Scratch (no cudaMalloc allowed): gathered atoms and per-atom S term.
__device__ float g_A[B_SZ * NA * D];   // [512][512]
__device__ float g_S[B_SZ * NA * D];   // [512][512]

typedef unsigned long long u64;

__device__ __forceinline__ u64 pack2(float lo, float hi) {
    u64 r; asm("mov.b64 %0, {%1, %2};" : "=l"(r) : "f"(lo), "f"(hi)); return r;
}
__device__ __forceinline__ void unpack2(u64 v, float& lo, float& hi) {
    asm("mov.b64 {%0, %1}, %2;" : "=f"(lo), "=f"(hi) : "l"(v));
}
// Packed fp32x2 FMA (sm_100+): 2x fp32 throughput vs 3-reg FFMA.
__device__ __forceinline__ void fma2(u64& acc, u64 a, u64 b) {
    asm("fma.rn.f32x2 %0, %1, %2, %0;" : "+l"(acc) : "l"(a), "l"(b));
}
__device__ __forceinline__ float gelu_exact(float x) {
    return 0.5f * x * (1.0f + erff(x * 0.70710678118654752440f));
}

// -------- Stage A: gather atom rows --------
__global__ void gather_kernel(const float* __restrict__ hs, const int* __restrict__ idx) {
    int r = blockIdx.x;            // 0..511
    int b = r / NA, n = r % NA;
    int t = idx[b * NA + n];
    t = t < 0 ? 0 : (t > T_SEQ - 1 ? T_SEQ - 1 : t);
    const float4* src = (const float4*)(hs + ((size_t)b * T_SEQ + t) * D);
    float4* dst = (float4*)(g_A + (size_t)r * D);
    for (int k = threadIdx.x; k < D / 4; k += blockDim.x) dst[k] = src[k];
}

// -------- Stage B: S = A @ W1a + 0.5*b1 (512x512x512) --------
__global__ void s_kernel(const float* __restrict__ W1, const float* __restrict__ b1) {
    __shared__ float sA[16][17];
    __shared__ float sB[16][17];
    int row = blockIdx.y * 16 + threadIdx.y;
    int col = blockIdx.x * 16 + threadIdx.x;
    float acc = 0.f;
    for (int k0 = 0; k0 < D; k0 += 16) {
        sA[threadIdx.y][threadIdx.x] = g_A[row * D + k0 + threadIdx.x];
        sB[threadIdx.y][threadIdx.x] = W1[(size_t)(k0 + threadIdx.y) * D + col];
        __syncthreads();
#pragma unroll
        for (int kk = 0; kk < 16; kk++) acc += sA[threadIdx.y][kk] * sB[kk][threadIdx.x];
        __syncthreads();
    }
    g_S[row * D + col] = acc + 0.5f * b1[col];
}

// -------- Stage C: fused pairwise GEMM + GELU + W2 reduce + mask --------
// CTA: 8 i-atoms x 8 j-atoms = 64 pairs; loops 4 N-chunks of 128; K blocked by 32.
// Thread (tx 0..15 covers 128 cols as 8 each; ty 0..15 covers 64 pairs as 2i x 2j).
// smem layout (floats):
//   sAi[8][520]      @ 0      (4160)
//   sAj[8][520]      @ 4160   (4160)
//   sW [2][32][128]  @ 8320   (8192)  double-buffered W1b k-slab
//   sSi[8][128]      @ 16512  (1024)
//   sSj[8][128]      @ 17536  (1024)
//   sW2[128][8]      @ 18560  (1024)
#define SM_FLOATS 19584

__global__ void __launch_bounds__(256, 2)
main_kernel(const float* __restrict__ W1, const float* __restrict__ W2,
            const float* __restrict__ b2, const int* __restrict__ mask,
            float* __restrict__ out) {
    extern __shared__ float sm[];
    float* sAi = sm;
    float* sAj = sm + 4160;
    float* sW  = sm + 8320;
    float* sSi = sm + 16512;
    float* sSj = sm + 17536;
    float* sW2 = sm + 18560;

    const int b = blockIdx.z;
    const int iBase = blockIdx.y * 8;
    const int jBase = blockIdx.x * 8;
    const int tid = threadIdx.x;
    const int tx = tid & 15;
    const int ty = tid >> 4;
    const int li0 = (ty >> 2) * 2, li1 = li0 + 1;
    const int lj0 = (ty & 3) * 2,  lj1 = lj0 + 1;

    // Load the 8+8 atom rows (full K=512) once.
    {
        const float* gAi = g_A + (size_t)(b * NA + iBase) * D;
        const float* gAj = g_A + (size_t)(b * NA + jBase) * D;
#pragma unroll
        for (int q = 0; q < 4; q++) {
            int f4 = tid + q * 256;
            int row = f4 >> 7;        // 128 float4 per row
            int c4  = f4 & 127;
            *(float4*)(sAi + row * 520 + c4 * 4) = *(const float4*)(gAi + row * D + c4 * 4);
            *(float4*)(sAj + row * 520 + c4 * 4) = *(const float4*)(gAj + row * D + c4 * 4);
        }
    }

    float p7[4][NB];
#pragma unroll
    for (int p = 0; p < 4; p++)
#pragma unroll
        for (int c = 0; c < NB; c++) p7[p][c] = 0.f;

    for (int chunk = 0; chunk < 4; chunk++) {
        __syncthreads();   // protect sS/sW2/sW from prior-iteration readers
        // S tiles for this chunk
        {
            int row = tid >> 5, c4 = tid & 31;
            const float* gSi = g_S + (size_t)(b * NA + iBase + row) * D + chunk * 128;
            const float* gSj = g_S + (size_t)(b * NA + jBase + row) * D + chunk * 128;
            *(float4*)(sSi + row * 128 + c4 * 4) = *(const float4*)(gSi + c4 * 4);
            *(float4*)(sSj + row * 128 + c4 * 4) = *(const float4*)(gSj + c4 * 4);
        }
        // W2 chunk (padded to 8 cols)
        if (tid < 128) {
            const float* w2p = W2 + (size_t)(chunk * 128 + tid) * NB;
#pragma unroll
            for (int c = 0; c < NB; c++) sW2[tid * 8 + c] = w2p[c];
            sW2[tid * 8 + 7] = 0.f;
        }
        // W1b k-block 0 into buffer 0
#pragma unroll
        for (int q = 0; q < 4; q++) {
            int f4 = tid + q * 256;
            int row = f4 >> 5, c4 = f4 & 31;
            *(float4*)(sW + row * 128 + c4 * 4) =
                *(const float4*)(W1 + (size_t)(D + row) * D + chunk * 128 + c4 * 4);
        }
        __syncthreads();

        u64 acc[16];
#pragma unroll
        for (int a = 0; a < 16; a++) acc[a] = 0ULL;

        for (int kb = 0; kb < 16; kb++) {
            const int cur = kb & 1;
            float4 pf[4];
            if (kb < 15) {            // prefetch next k-slab into registers
#pragma unroll
                for (int q = 0; q < 4; q++) {
                    int f4 = tid + q * 256;
                    int row = f4 >> 5, c4 = f4 & 31;
                    pf[q] = *(const float4*)(W1 + (size_t)(D + (kb + 1) * 32 + row) * D
                                             + chunk * 128 + c4 * 4);
                }
            }
            const float* swp = sW + cur * 4096;
#pragma unroll
            for (int kk = 0; kk < 32; kk += 4) {
                const int k0 = kb * 32 + kk;
                float4 AI0 = *(const float4*)(sAi + li0 * 520 + k0);
                float4 AI1 = *(const float4*)(sAi + li1 * 520 + k0);
                float4 AJ0 = *(const float4*)(sAj + lj0 * 520 + k0);
                float4 AJ1 = *(const float4*)(sAj + lj1 * 520 + k0);
                float ai0[4] = {AI0.x, AI0.y, AI0.z, AI0.w};
                float ai1[4] = {AI1.x, AI1.y, AI1.z, AI1.w};
                float aj0[4] = {AJ0.x, AJ0.y, AJ0.z, AJ0.w};
                float aj1[4] = {AJ1.x, AJ1.y, AJ1.z, AJ1.w};
#pragma unroll
                for (int u = 0; u < 4; u++) {
                    const ulonglong2* wr = (const ulonglong2*)(swp + (kk + u) * 128 + tx * 8);
                    ulonglong2 wA = wr[0];
                    ulonglong2 wB = wr[1];
                    float d00f = fabsf(ai0[u] - aj0[u]);
                    float d01f = fabsf(ai0[u] - aj1[u]);
                    float d10f = fabsf(ai1[u] - aj0[u]);
                    float d11f = fabsf(ai1[u] - aj1[u]);
                    u64 d00 = pack2(d00f, d00f);
                    u64 d01 = pack2(d01f, d01f);
                    u64 d10 = pack2(d10f, d10f);
                    u64 d11 = pack2(d11f, d11f);
                    fma2(acc[0],  d00, wA.x); fma2(acc[1],  d00, wA.y);
                    fma2(acc[2],  d00, wB.x); fma2(acc[3],  d00, wB.y);
                    fma2(acc[4],  d01, wA.x); fma2(acc[5],  d01, wA.y);
                    fma2(acc[6],  d01, wB.x); fma2(acc[7],  d01, wB.y);
                    fma2(acc[8],  d10, wA.x); fma2(acc[9],  d10, wA.y);
                    fma2(acc[10], d10, wB.x); fma2(acc[11], d10, wB.y);
                    fma2(acc[12], d11, wA.x); fma2(acc[13], d11, wA.y);
                    fma2(acc[14], d11, wB.x); fma2(acc[15], d11, wB.y);
                }
            }
            // Store prefetched slab into the *other* buffer. Safe without a
            // pre-sync: writers touch 1-cur, any laggards read cur (disjoint).
            if (kb < 15) {
                float* dstW = sW + (1 - cur) * 4096;
#pragma unroll
                for (int q = 0; q < 4; q++) {
                    int f4 = tid + q * 256;
                    int row = f4 >> 5, c4 = f4 & 31;
                    *(float4*)(dstW + row * 128 + c4 * 4) = pf[q];
                }
            }
            __syncthreads();
        }

        // Epilogue: v = acc + S_i + S_j -> exact GELU -> reduce with W2 chunk.
#pragma unroll
        for (int c2 = 0; c2 < 4; c2++) {
            const int c = tx * 8 + c2 * 2;
            float w2a[NB], w2b[NB];
#pragma unroll
            for (int c7 = 0; c7 < NB; c7++) {
                w2a[c7] = sW2[c * 8 + c7];
                w2b[c7] = sW2[(c + 1) * 8 + c7];
            }
#pragma unroll
            for (int p = 0; p < 4; p++) {
                const int li = li0 + (p >> 1);
                const int lj = lj0 + (p & 1);
                float lo, hi; unpack2(acc[p * 4 + c2], lo, hi);
                float v0 = lo + sSi[li * 128 + c]     + sSj[lj * 128 + c];
                float v1 = hi + sSi[li * 128 + c + 1] + sSj[lj * 128 + c + 1];
                float g0 = gelu_exact(v0);
                float g1 = gelu_exact(v1);
#pragma unroll
                for (int c7 = 0; c7 < NB; c7++) p7[p][c7] += g0 * w2a[c7] + g1 * w2b[c7];
            }
        }
    }

    // Final: reduce the 16 tx-lanes (within 16-lane shuffle groups), mask, store.
#pragma unroll
    for (int p = 0; p < 4; p++) {
        const int i = iBase + li0 + (p >> 1);
        const int j = jBase + lj0 + (p & 1);
        const bool valid = (mask[b * NA + i] != 0) && (mask[b * NA + j] != 0) && (i != j);
#pragma unroll
        for (int c7 = 0; c7 < NB; c7++) {
            float v = p7[p][c7];
            v += __shfl_xor_sync(0xffffffffu, v, 1);
            v += __shfl_xor_sync(0xffffffffu, v, 2);
            v += __shfl_xor_sync(0xffffffffu, v, 4);
            v += __shfl_xor_sync(0xffffffffu, v, 8);
            if (tx == 0)
                out[(((size_t)b * NB + c7) * NA + i) * NA + j] =
                    valid ? (v + b2[c7]) : MASK_FILL;
        }
    }
}

extern "C" void kernel_launch(void* const* d_in, const int* in_sizes, int n_in,
                              void* d_out, int out_size) {
    (void)in_sizes; (void)n_in; (void)out_size;
    const float* hs = (const float*)d_in[0];
    const float* W1 = (const float*)d_in[1];
    const float* b1 = (const float*)d_in[2];
    const float* W2 = (const float*)d_in[3];
    const float* b2 = (const float*)d_in[4];
    const int* idx  = (const int*)d_in[5];
    const int* msk  = (const int*)d_in[6];
    float* out = (float*)d_out;

    gather_kernel<<<B_SZ * NA, 128>>>(hs, idx);
    s_kernel<<<dim3(D / 16, (B_SZ * NA) / 16), dim3(16, 16)>>>(W1, b1);

    size_t smem = SM_FLOATS * sizeof(float);
    cudaFuncSetAttribute(main_kernel, cudaFuncAttributeMaxDynamicSharedMemorySize, (int)smem);
    main_kernel<<<dim3(NA / 8, NA / 8, B_SZ), 256, smem>>>(W1, W2, b2, msk, out);
}

// round 5
// speedup vs baseline: 6.4122x; 6.4122x over previous
#include <cuda_runtime.h>
#include <cuda_bf16.h>
#include <cstdint>

#define D 512
#define NA 256
#define B_SZ 2
#define T_SEQ 1024
#define NB 7
#define MASK_FILL -10000.0f

#define TI 8
#define TJ 16

// smem byte offsets (all 16B aligned; pitches chosen so ldmatrix is conflict-free)
#define AP_B   1040              // A row pitch bytes (520 bf16 = 65 x 16B)
#define BP_B   144               // B slab row pitch bytes (72 bf16 = 9 x 16B)
#define HP_B   272               // h row pitch bytes (136 bf16 = 17 x 16B)
#define WP_B   1040              // W2t row pitch bytes
#define OFF_A  0                 // 128 x 1040 = 133120
#define OFF_B  133120            // 2 x 18432 = 36864
#define BBUF   18432
#define OFF_H  169984            // 128 x 272 = 34816
#define OFF_W2T 204800           // 8 x 1040 = 8320
#define SMEM_REQ 213120

__device__ float g_A[B_SZ * NA * D];
__device__ float g_S[B_SZ * NA * D];
__device__ __nv_bfloat16 g_Wt[D * D];       // W1b^T: [n][k]
__device__ __nv_bfloat16 g_W2t[8 * D];      // W2^T padded: [c][k], c=7 zeros

__device__ __forceinline__ uint32_t smem_u32(const void* p) {
    uint32_t a;
    asm("{ .reg .u64 t; cvta.to.shared.u64 t, %1; cvt.u32.u64 %0, t; }" : "=r"(a) : "l"(p));
    return a;
}
__device__ __forceinline__ uint32_t pack_bf16x2(float lo, float hi) {
    uint32_t r;
    asm("cvt.rn.bf16x2.f32 %0, %1, %2;" : "=r"(r) : "f"(hi), "f"(lo));
    return r;
}
__device__ __forceinline__ float gelu_exact(float x) {
    return 0.5f * x * (1.0f + erff(x * 0.70710678118654752440f));
}

#define LDSM4(r, addr) \
    asm volatile("ldmatrix.sync.aligned.m8n8.x4.shared.b16 {%0,%1,%2,%3}, [%4];" \
        : "=r"((r)[0]), "=r"((r)[1]), "=r"((r)[2]), "=r"((r)[3]) : "r"(addr))
#define LDSM2(r0, r1, addr) \
    asm volatile("ldmatrix.sync.aligned.m8n8.x2.shared.b16 {%0,%1}, [%2];" \
        : "=r"(r0), "=r"(r1) : "r"(addr))
#define MMA16816(d, a, b0_, b1_) \
    asm volatile("mma.sync.aligned.m16n8k16.row.col.f32.bf16.bf16.f32 " \
        "{%0,%1,%2,%3}, {%4,%5,%6,%7}, {%8,%9}, {%0,%1,%2,%3};" \
        : "+f"((d)[0]), "+f"((d)[1]), "+f"((d)[2]), "+f"((d)[3]) \
        : "r"((a)[0]), "r"((a)[1]), "r"((a)[2]), "r"((a)[3]), "r"(b0_), "r"(b1_))
#define CP16(dst, src)  asm volatile("cp.async.cg.shared.global [%0], [%1], 16;" :: "r"(dst), "l"(src))
#define CP_COMMIT()     asm volatile("cp.async.commit_group;" ::: "memory")
#define CP_WAIT1()      asm volatile("cp.async.wait_group 1;" ::: "memory")
#define CP_WAIT0()      asm volatile("cp.async.wait_group 0;" ::: "memory")

// ---------------- prep kernels ----------------
__global__ void gather_kernel(const float* __restrict__ hs, const int* __restrict__ idx) {
    int r = blockIdx.x;
    int b = r / NA, n = r % NA;
    int t = idx[b * NA + n];
    t = t < 0 ? 0 : (t > T_SEQ - 1 ? T_SEQ - 1 : t);
    const float4* src = (const float4*)(hs + ((size_t)b * T_SEQ + t) * D);
    float4* dst = (float4*)(g_A + (size_t)r * D);
    for (int k = threadIdx.x; k < D / 4; k += blockDim.x) dst[k] = src[k];
}

__global__ void s_kernel(const float* __restrict__ W1, const float* __restrict__ b1) {
    __shared__ float sA[16][17];
    __shared__ float sB[16][17];
    int row = blockIdx.y * 16 + threadIdx.y;
    int col = blockIdx.x * 16 + threadIdx.x;
    float acc = 0.f;
    for (int k0 = 0; k0 < D; k0 += 16) {
        sA[threadIdx.y][threadIdx.x] = g_A[row * D + k0 + threadIdx.x];
        sB[threadIdx.y][threadIdx.x] = W1[(size_t)(k0 + threadIdx.y) * D + col];
        __syncthreads();
#pragma unroll
        for (int kk = 0; kk < 16; kk++) acc += sA[threadIdx.y][kk] * sB[kk][threadIdx.x];
        __syncthreads();
    }
    g_S[row * D + col] = acc + 0.5f * b1[col];
}

__global__ void wt_kernel(const float* __restrict__ W1) {
    __shared__ float t[32][33];
    int n0 = blockIdx.x * 32, k0 = blockIdx.y * 32;
    int tx = threadIdx.x, ty = threadIdx.y;   // 32 x 8
#pragma unroll
    for (int q = 0; q < 4; q++)
        t[ty + 8 * q][tx] = W1[(size_t)(D + k0 + ty + 8 * q) * D + n0 + tx];
    __syncthreads();
#pragma unroll
    for (int q = 0; q < 4; q++)
        g_Wt[(size_t)(n0 + ty + 8 * q) * D + k0 + tx] = __float2bfloat16(t[tx][ty + 8 * q]);
}

__global__ void w2t_kernel(const float* __restrict__ W2) {
    int k = threadIdx.x;   // 512 threads
#pragma unroll
    for (int c = 0; c < 8; c++)
        g_W2t[c * D + k] = (c < NB) ? __float2bfloat16(W2[(size_t)k * NB + c])
                                    : __float2bfloat16(0.f);
}

// ---------------- main pairwise kernel (mma.sync bf16) ----------------
__global__ void __launch_bounds__(256, 1)
pair_kernel(const float* __restrict__ b2, const int* __restrict__ mask,
            float* __restrict__ out) {
    extern __shared__ __align__(1024) char sm[];
    const uint32_t smb = smem_u32(sm);

    const int tid  = threadIdx.x;
    const int wid  = tid >> 5;
    const int lane = tid & 31;
    const int wm = wid >> 2;       // 0..1  (M warp row)
    const int wn = wid & 3;        // 0..3  (N warp col)
    const int gid = lane >> 2;     // 0..7
    const int tig = lane & 3;      // 0..3

    const int b = blockIdx.z;
    const int iBase = blockIdx.y * TI;
    const int jBase = blockIdx.x * TJ;

    // ---- build A = |a_i - a_j| bf16 into smem [128][520] ----
    {
        const float* Ai = g_A + (size_t)(b * NA + iBase) * D;
        const float* Aj = g_A + (size_t)(b * NA + jBase) * D;
#pragma unroll 4
        for (int it = 0; it < 128; it++) {
            int idx = tid + it * 256;          // 0..32767
            int p = idx >> 8, kp = idx & 255;  // k = 2*kp
            float2 a = __ldg((const float2*)(Ai + (size_t)(p >> 4) * D + kp * 2));
            float2 c = __ldg((const float2*)(Aj + (size_t)(p & 15) * D + kp * 2));
            *(uint32_t*)(sm + OFF_A + p * AP_B + kp * 4) =
                pack_bf16x2(fabsf(a.x - c.x), fabsf(a.y - c.y));
        }
    }
    // ---- W2t -> smem [8][520] ----
#pragma unroll
    for (int q = 0; q < 8; q++) {
        int id = tid + q * 256;                // 0..2047
        int c = id >> 8, k2 = id & 255;        // bf16x2 index
        *(uint32_t*)(sm + OFF_W2T + c * WP_B + k2 * 4) =
            *(const uint32_t*)((const char*)g_W2t + ((size_t)c * D + k2 * 2) * 2);
    }
    __syncthreads();

    float la[4] = {0.f, 0.f, 0.f, 0.f};   // logits accum (pairs gid/gid+8, cols tig*2,+1)

    for (int chunk = 0; chunk < 4; chunk++) {
        float acc[4][4][4];
#pragma unroll
        for (int mt = 0; mt < 4; mt++)
#pragma unroll
            for (int nt = 0; nt < 4; nt++)
#pragma unroll
                for (int r = 0; r < 4; r++) acc[mt][nt][r] = 0.f;

        // pre-issue B slab 0 of this chunk
        {
            const __nv_bfloat16* src = g_Wt + ((size_t)(chunk * 128) << 9);
#pragma unroll
            for (int q = 0; q < 4; q++) {
                int id = tid + q * 256;
                int n = id >> 3, c16 = id & 7;
                CP16(smb + OFF_B + n * BP_B + c16 * 16, src + (size_t)n * D + c16 * 8);
            }
            CP_COMMIT();
        }

        for (int ks = 0; ks < 8; ks++) {
            __syncthreads();                     // prior reads of buf[(ks+1)&1] done
            if (ks < 7) {
                const __nv_bfloat16* src = g_Wt + ((size_t)(chunk * 128) << 9) + (ks + 1) * 64;
                uint32_t dbase = smb + OFF_B + ((ks + 1) & 1) * BBUF;
#pragma unroll
                for (int q = 0; q < 4; q++) {
                    int id = tid + q * 256;
                    int n = id >> 3, c16 = id & 7;
                    CP16(dbase + n * BP_B + c16 * 16, src + (size_t)n * D + c16 * 8);
                }
                CP_COMMIT();
                CP_WAIT1();
            } else {
                CP_WAIT0();
            }
            __syncthreads();                     // slab ks visible to all

            const uint32_t bbase = smb + OFF_B + (ks & 1) * BBUF;
#pragma unroll
            for (int kk = 0; kk < 4; kk++) {
                const int kg = ks * 64 + kk * 16;
                uint32_t af[4][4];
#pragma unroll
                for (int mt = 0; mt < 4; mt++) {
                    uint32_t addr = smb + OFF_A
                        + (uint32_t)(wm * 64 + mt * 16 + (lane & 15)) * AP_B
                        + (uint32_t)(kg + (lane >> 4) * 8) * 2;
                    LDSM4(af[mt], addr);
                }
#pragma unroll
                for (int bt = 0; bt < 2; bt++) {
                    uint32_t r0, r1, r2, r3;
                    uint32_t addr = bbase
                        + (uint32_t)(wn * 32 + bt * 16 + (lane & 15)) * BP_B
                        + (uint32_t)(kk * 16 + (lane >> 4) * 8) * 2;
                    uint32_t rr[4];
                    LDSM4(rr, addr);
                    r0 = rr[0]; r1 = rr[1]; r2 = rr[2]; r3 = rr[3];
#pragma unroll
                    for (int mt = 0; mt < 4; mt++) {
                        MMA16816(acc[mt][bt * 2 + 0], af[mt], r0, r2);
                        MMA16816(acc[mt][bt * 2 + 1], af[mt], r1, r3);
                    }
                }
            }
        }

        // ---- epilogue: + S_i + S_j, GELU, h -> smem bf16 ----
        const float* Sb = g_S + ((size_t)b * NA) * D + chunk * 128;
#pragma unroll
        for (int nt = 0; nt < 4; nt++) {
            const int cl = wn * 32 + nt * 8 + tig * 2;
            float2 sj0 = __ldg((const float2*)(Sb + (size_t)(jBase + gid) * D + cl));
            float2 sj8 = __ldg((const float2*)(Sb + (size_t)(jBase + gid + 8) * D + cl));
#pragma unroll
            for (int mt = 0; mt < 4; mt++) {
                float2 si = __ldg((const float2*)(Sb + (size_t)(iBase + wm * 4 + mt) * D + cl));
                float v0 = acc[mt][nt][0] + si.x + sj0.x;
                float v1 = acc[mt][nt][1] + si.y + sj0.y;
                float v2 = acc[mt][nt][2] + si.x + sj8.x;
                float v3 = acc[mt][nt][3] + si.y + sj8.y;
                uint32_t h01 = pack_bf16x2(gelu_exact(v0), gelu_exact(v1));
                uint32_t h23 = pack_bf16x2(gelu_exact(v2), gelu_exact(v3));
                const int p0 = wm * 64 + mt * 16 + gid;
                *(uint32_t*)(sm + OFF_H + p0 * HP_B + cl * 2) = h01;
                *(uint32_t*)(sm + OFF_H + (p0 + 8) * HP_B + cl * 2) = h23;
            }
        }
        __syncthreads();

        // ---- logits mma: h[16 pairs][128] x W2t -> la (warp wid owns pairs 16*wid..+15) ----
#pragma unroll
        for (int kk = 0; kk < 8; kk++) {
            uint32_t a[4];
            uint32_t aaddr = smb + OFF_H
                + (uint32_t)(wid * 16 + (lane & 15)) * HP_B
                + (uint32_t)(kk * 16 + (lane >> 4) * 8) * 2;
            LDSM4(a, aaddr);
            uint32_t b0, b1;
            uint32_t baddr = smb + OFF_W2T
                + (uint32_t)(lane & 7) * WP_B
                + (uint32_t)(chunk * 128 + kk * 16 + ((lane >> 3) & 1) * 8) * 2;
            LDSM2(b0, b1, baddr);
            MMA16816(la, a, b0, b1);
        }
        // next iteration's first __syncthreads covers h reuse
    }

    // ---- store: la maps (pair gid / gid+8 of warp) x (cols tig*2, tig*2+1) ----
    const int c0 = tig * 2, c1 = c0 + 1;
    const float bias0 = __ldg(b2 + c0);
    const float bias1 = (c1 < NB) ? __ldg(b2 + c1) : 0.f;
#pragma unroll
    for (int h = 0; h < 2; h++) {
        const int p = wid * 16 + gid + h * 8;
        const int i = iBase + (p >> 4);
        const int j = jBase + (p & 15);
        const bool valid = (__ldg(mask + b * NA + i) != 0) &&
                           (__ldg(mask + b * NA + j) != 0) && (i != j);
        float v0 = la[h * 2 + 0] + bias0;
        out[(((size_t)b * NB + c0) * NA + i) * NA + j] = valid ? v0 : MASK_FILL;
        if (c1 < NB) {
            float v1 = la[h * 2 + 1] + bias1;
            out[(((size_t)b * NB + c1) * NA + i) * NA + j] = valid ? v1 : MASK_FILL;
        }
    }
}

extern "C" void kernel_launch(void* const* d_in, const int* in_sizes, int n_in,
                              void* d_out, int out_size) {
    (void)in_sizes; (void)n_in; (void)out_size;
    const float* hs = (const float*)d_in[0];
    const float* W1 = (const float*)d_in[1];
    const float* b1 = (const float*)d_in[2];
    const float* W2 = (const float*)d_in[3];
    const float* b2 = (const float*)d_in[4];
    const int* idx  = (const int*)d_in[5];
    const int* msk  = (const int*)d_in[6];
    float* out = (float*)d_out;

    gather_kernel<<<B_SZ * NA, 128>>>(hs, idx);
    s_kernel<<<dim3(D / 16, (B_SZ * NA) / 16), dim3(16, 16)>>>(W1, b1);
    wt_kernel<<<dim3(D / 32, D / 32), dim3(32, 8)>>>(W1);
    w2t_kernel<<<1, 512>>>(W2);

    cudaFuncSetAttribute(pair_kernel, cudaFuncAttributeMaxDynamicSharedMemorySize, SMEM_REQ);
    pair_kernel<<<dim3(NA / TJ, NA / TI, B_SZ), 256, SMEM_REQ>>>(b2, msk, out);
}

// round 6
// speedup vs baseline: 10.7153x; 1.6711x over previous
#include <cuda_runtime.h>
#include <cuda_bf16.h>
#include <cstdint>

#define D 512
#define NA 256
#define B_SZ 2
#define T_SEQ 1024
#define NB 7
#define MASK_FILL -10000.0f

#define TI 8
#define TJ 16
#define NBLK 272   // triangular blocks per batch: sum_{bj=0..15} (2*bj+2)

// smem byte offsets (16B aligned; pitches keep ldmatrix conflict-free)
#define AP_B   1040
#define BP_B   144
#define HP_B   272
#define WP_B   1040
#define OFF_A  0
#define OFF_B  133120
#define BBUF   18432
#define OFF_H  169984
#define OFF_W2T 204800
#define SMEM_REQ 213120

__device__ float g_A[B_SZ * NA * D];
__device__ float g_S[B_SZ * NA * D];
__device__ __nv_bfloat16 g_Wt[D * D];       // W1b^T: [n][k]
__device__ __nv_bfloat16 g_W2t[8 * D];      // W2^T padded: [c][k]

__device__ __forceinline__ uint32_t smem_u32(const void* p) {
    uint32_t a;
    asm("{ .reg .u64 t; cvta.to.shared.u64 t, %1; cvt.u32.u64 %0, t; }" : "=r"(a) : "l"(p));
    return a;
}
__device__ __forceinline__ uint32_t pack_bf16x2(float lo, float hi) {
    uint32_t r;
    asm("cvt.rn.bf16x2.f32 %0, %1, %2;" : "=r"(r) : "f"(hi), "f"(lo));
    return r;
}
__device__ __forceinline__ float gelu_exact(float x) {
    return 0.5f * x * (1.0f + erff(x * 0.70710678118654752440f));
}

#define LDSM4(r, addr) \
    asm volatile("ldmatrix.sync.aligned.m8n8.x4.shared.b16 {%0,%1,%2,%3}, [%4];" \
        : "=r"((r)[0]), "=r"((r)[1]), "=r"((r)[2]), "=r"((r)[3]) : "r"(addr))
#define LDSM2(r0, r1, addr) \
    asm volatile("ldmatrix.sync.aligned.m8n8.x2.shared.b16 {%0,%1}, [%2];" \
        : "=r"(r0), "=r"(r1) : "r"(addr))
#define MMA16816(d, a, b0_, b1_) \
    asm volatile("mma.sync.aligned.m16n8k16.row.col.f32.bf16.bf16.f32 " \
        "{%0,%1,%2,%3}, {%4,%5,%6,%7}, {%8,%9}, {%0,%1,%2,%3};" \
        : "+f"((d)[0]), "+f"((d)[1]), "+f"((d)[2]), "+f"((d)[3]) \
        : "r"((a)[0]), "r"((a)[1]), "r"((a)[2]), "r"((a)[3]), "r"(b0_), "r"(b1_))
#define CP16(dst, src)  asm volatile("cp.async.cg.shared.global [%0], [%1], 16;" :: "r"(dst), "l"(src))
#define CP_COMMIT()     asm volatile("cp.async.commit_group;" ::: "memory")
#define CP_WAIT1()      asm volatile("cp.async.wait_group 1;" ::: "memory")
#define CP_WAIT0()      asm volatile("cp.async.wait_group 0;" ::: "memory")

// ---------------- prep kernels ----------------
__global__ void gather_kernel(const float* __restrict__ hs, const int* __restrict__ idx) {
    int r = blockIdx.x;
    int b = r / NA, n = r % NA;
    int t = idx[b * NA + n];
    t = t < 0 ? 0 : (t > T_SEQ - 1 ? T_SEQ - 1 : t);
    const float4* src = (const float4*)(hs + ((size_t)b * T_SEQ + t) * D);
    float4* dst = (float4*)(g_A + (size_t)r * D);
    for (int k = threadIdx.x; k < D / 4; k += blockDim.x) dst[k] = src[k];
}

// S = A @ W1a + 0.5*b1.  32x32 tiles, 256 CTAs, 4 outputs/thread.
__global__ void s_kernel(const float* __restrict__ W1, const float* __restrict__ b1) {
    __shared__ float sA[32][33];
    __shared__ float sB[32][36];
    const int tid = threadIdx.x;
    const int r = tid >> 3;          // 0..31
    const int cq = (tid & 7) * 4;    // 0,4,..28
    const int rowBase = blockIdx.y * 32;
    const int colBase = blockIdx.x * 32;
    float4 acc = make_float4(0.f, 0.f, 0.f, 0.f);
    for (int k0 = 0; k0 < D; k0 += 32) {
        float4 av = *(const float4*)(g_A + (size_t)(rowBase + r) * D + k0 + cq);
        sA[r][cq] = av.x; sA[r][cq + 1] = av.y; sA[r][cq + 2] = av.z; sA[r][cq + 3] = av.w;
        *(float4*)(&sB[r][cq]) = *(const float4*)(W1 + (size_t)(k0 + r) * D + colBase + cq);
        __syncthreads();
#pragma unroll
        for (int k = 0; k < 32; k++) {
            float a = sA[r][k];
            float4 bv = *(float4*)(&sB[k][cq]);
            acc.x += a * bv.x; acc.y += a * bv.y; acc.z += a * bv.z; acc.w += a * bv.w;
        }
        __syncthreads();
    }
    float4 bb = *(const float4*)(b1 + colBase + cq);
    acc.x += 0.5f * bb.x; acc.y += 0.5f * bb.y; acc.z += 0.5f * bb.z; acc.w += 0.5f * bb.w;
    *(float4*)(g_S + (size_t)(rowBase + r) * D + colBase + cq) = acc;
}

__global__ void wt_kernel(const float* __restrict__ W1) {
    __shared__ float t[32][33];
    int n0 = blockIdx.x * 32, k0 = blockIdx.y * 32;
    int tx = threadIdx.x, ty = threadIdx.y;   // 32 x 8
#pragma unroll
    for (int q = 0; q < 4; q++)
        t[ty + 8 * q][tx] = W1[(size_t)(D + k0 + ty + 8 * q) * D + n0 + tx];
    __syncthreads();
#pragma unroll
    for (int q = 0; q < 4; q++)
        g_Wt[(size_t)(n0 + ty + 8 * q) * D + k0 + tx] = __float2bfloat16(t[tx][ty + 8 * q]);
}

__global__ void w2t_kernel(const float* __restrict__ W2) {
    int k = threadIdx.x;
#pragma unroll
    for (int c = 0; c < 8; c++)
        g_W2t[c * D + k] = (c < NB) ? __float2bfloat16(W2[(size_t)k * NB + c])
                                    : __float2bfloat16(0.f);
}

// ---------------- main pairwise kernel (triangular grid) ----------------
__global__ void __launch_bounds__(256, 1)
pair_kernel(const float* __restrict__ b2, const int* __restrict__ mask,
            float* __restrict__ out) {
    extern __shared__ __align__(1024) char sm[];
    const uint32_t smb = smem_u32(sm);

    const int tid  = threadIdx.x;
    const int wid  = tid >> 5;
    const int lane = tid & 31;
    const int wm = wid >> 2;
    const int wn = wid & 3;
    const int gid = lane >> 2;
    const int tig = lane & 3;

    const int b = blockIdx.z;
    // invert id = bj^2 + bj + bi  (bi in 0..2*bj+1)
    const int id = blockIdx.x;
    int bj = (int)((sqrtf(4.f * (float)id + 1.f) - 1.f) * 0.5f);
    while ((bj + 1) * (bj + 2) <= id) bj++;
    while (bj * (bj + 1) > id) bj--;
    const int bi = id - bj * (bj + 1);
    const int iBase = bi * TI;
    const int jBase = bj * TJ;

    // ---- build A = |a_i - a_j| bf16 into smem [128][520] ----
    {
        const float* Ai = g_A + (size_t)(b * NA + iBase) * D;
        const float* Aj = g_A + (size_t)(b * NA + jBase) * D;
#pragma unroll 4
        for (int it = 0; it < 128; it++) {
            int idx = tid + it * 256;
            int p = idx >> 8, kp = idx & 255;
            float2 a = __ldg((const float2*)(Ai + (size_t)(p >> 4) * D + kp * 2));
            float2 c = __ldg((const float2*)(Aj + (size_t)(p & 15) * D + kp * 2));
            *(uint32_t*)(sm + OFF_A + p * AP_B + kp * 4) =
                pack_bf16x2(fabsf(a.x - c.x), fabsf(a.y - c.y));
        }
    }
    // ---- W2t -> smem [8][520] ----
#pragma unroll
    for (int q = 0; q < 8; q++) {
        int idq = tid + q * 256;
        int c = idq >> 8, k2 = idq & 255;
        *(uint32_t*)(sm + OFF_W2T + c * WP_B + k2 * 4) =
            *(const uint32_t*)((const char*)g_W2t + ((size_t)c * D + k2 * 2) * 2);
    }
    __syncthreads();

    float la[4] = {0.f, 0.f, 0.f, 0.f};

    for (int chunk = 0; chunk < 4; chunk++) {
        float acc[4][4][4];
#pragma unroll
        for (int mt = 0; mt < 4; mt++)
#pragma unroll
            for (int nt = 0; nt < 4; nt++)
#pragma unroll
                for (int r = 0; r < 4; r++) acc[mt][nt][r] = 0.f;

        {
            const __nv_bfloat16* src = g_Wt + ((size_t)(chunk * 128) << 9);
#pragma unroll
            for (int q = 0; q < 4; q++) {
                int idq = tid + q * 256;
                int n = idq >> 3, c16 = idq & 7;
                CP16(smb + OFF_B + n * BP_B + c16 * 16, src + (size_t)n * D + c16 * 8);
            }
            CP_COMMIT();
        }

        for (int ks = 0; ks < 8; ks++) {
            __syncthreads();
            if (ks < 7) {
                const __nv_bfloat16* src = g_Wt + ((size_t)(chunk * 128) << 9) + (ks + 1) * 64;
                uint32_t dbase = smb + OFF_B + ((ks + 1) & 1) * BBUF;
#pragma unroll
                for (int q = 0; q < 4; q++) {
                    int idq = tid + q * 256;
                    int n = idq >> 3, c16 = idq & 7;
                    CP16(dbase + n * BP_B + c16 * 16, src + (size_t)n * D + c16 * 8);
                }
                CP_COMMIT();
                CP_WAIT1();
            } else {
                CP_WAIT0();
            }
            __syncthreads();

            const uint32_t bbase = smb + OFF_B + (ks & 1) * BBUF;
#pragma unroll
            for (int kk = 0; kk < 4; kk++) {
                const int kg = ks * 64 + kk * 16;
                uint32_t af[4][4];
#pragma unroll
                for (int mt = 0; mt < 4; mt++) {
                    uint32_t addr = smb + OFF_A
                        + (uint32_t)(wm * 64 + mt * 16 + (lane & 15)) * AP_B
                        + (uint32_t)(kg + (lane >> 4) * 8) * 2;
                    LDSM4(af[mt], addr);
                }
#pragma unroll
                for (int bt = 0; bt < 2; bt++) {
                    uint32_t addr = bbase
                        + (uint32_t)(wn * 32 + bt * 16 + (lane & 15)) * BP_B
                        + (uint32_t)(kk * 16 + (lane >> 4) * 8) * 2;
                    uint32_t rr[4];
                    LDSM4(rr, addr);
#pragma unroll
                    for (int mt = 0; mt < 4; mt++) {
                        MMA16816(acc[mt][bt * 2 + 0], af[mt], rr[0], rr[2]);
                        MMA16816(acc[mt][bt * 2 + 1], af[mt], rr[1], rr[3]);
                    }
                }
            }
        }

        // ---- epilogue: + S_i + S_j, GELU, h -> smem bf16 ----
        const float* Sb = g_S + ((size_t)b * NA) * D + chunk * 128;
#pragma unroll
        for (int nt = 0; nt < 4; nt++) {
            const int cl = wn * 32 + nt * 8 + tig * 2;
            float2 sj0 = __ldg((const float2*)(Sb + (size_t)(jBase + gid) * D + cl));
            float2 sj8 = __ldg((const float2*)(Sb + (size_t)(jBase + gid + 8) * D + cl));
#pragma unroll
            for (int mt = 0; mt < 4; mt++) {
                float2 si = __ldg((const float2*)(Sb + (size_t)(iBase + wm * 4 + mt) * D + cl));
                float v0 = acc[mt][nt][0] + si.x + sj0.x;
                float v1 = acc[mt][nt][1] + si.y + sj0.y;
                float v2 = acc[mt][nt][2] + si.x + sj8.x;
                float v3 = acc[mt][nt][3] + si.y + sj8.y;
                uint32_t h01 = pack_bf16x2(gelu_exact(v0), gelu_exact(v1));
                uint32_t h23 = pack_bf16x2(gelu_exact(v2), gelu_exact(v3));
                const int p0 = wm * 64 + mt * 16 + gid;
                *(uint32_t*)(sm + OFF_H + p0 * HP_B + cl * 2) = h01;
                *(uint32_t*)(sm + OFF_H + (p0 + 8) * HP_B + cl * 2) = h23;
            }
        }
        __syncthreads();

        // ---- logits mma ----
#pragma unroll
        for (int kk = 0; kk < 8; kk++) {
            uint32_t a[4];
            uint32_t aaddr = smb + OFF_H
                + (uint32_t)(wid * 16 + (lane & 15)) * HP_B
                + (uint32_t)(kk * 16 + (lane >> 4) * 8) * 2;
            LDSM4(a, aaddr);
            uint32_t b0, b1;
            uint32_t baddr = smb + OFF_W2T
                + (uint32_t)(lane & 7) * WP_B
                + (uint32_t)(chunk * 128 + kk * 16 + ((lane >> 3) & 1) * 8) * 2;
            LDSM2(b0, b1, baddr);
            MMA16816(la, a, b0, b1);
        }
    }

    // ---- store with mirror: compute (i,j) i<=j, write (i,j) and (j,i) ----
    const int c0 = tig * 2, c1 = c0 + 1;
    const float bias0 = __ldg(b2 + c0);
    const float bias1 = (c1 < NB) ? __ldg(b2 + c1) : 0.f;
    float* ob = out + (size_t)b * NB * NA * NA;
#pragma unroll
    for (int h = 0; h < 2; h++) {
        const int p = wid * 16 + gid + h * 8;
        const int i = iBase + (p >> 4);
        const int j = jBase + (p & 15);
        if (i > j) continue;
        if (i == j) {
            ob[(size_t)c0 * NA * NA + i * NA + j] = MASK_FILL;
            if (c1 < NB) ob[(size_t)c1 * NA * NA + i * NA + j] = MASK_FILL;
            continue;
        }
        const bool valid = (__ldg(mask + b * NA + i) != 0) &&
                           (__ldg(mask + b * NA + j) != 0);
        float v0 = valid ? (la[h * 2 + 0] + bias0) : MASK_FILL;
        ob[(size_t)c0 * NA * NA + i * NA + j] = v0;
        ob[(size_t)c0 * NA * NA + j * NA + i] = v0;
        if (c1 < NB) {
            float v1 = valid ? (la[h * 2 + 1] + bias1) : MASK_FILL;
            ob[(size_t)c1 * NA * NA + i * NA + j] = v1;
            ob[(size_t)c1 * NA * NA + j * NA + i] = v1;
        }
    }
}

extern "C" void kernel_launch(void* const* d_in, const int* in_sizes, int n_in,
                              void* d_out, int out_size) {
    (void)in_sizes; (void)n_in; (void)out_size;
    const float* hs = (const float*)d_in[0];
    const float* W1 = (const float*)d_in[1];
    const float* b1 = (const float*)d_in[2];
    const float* W2 = (const float*)d_in[3];
    const float* b2 = (const float*)d_in[4];
    const int* idx  = (const int*)d_in[5];
    const int* msk  = (const int*)d_in[6];
    float* out = (float*)d_out;

    gather_kernel<<<B_SZ * NA, 128>>>(hs, idx);
    s_kernel<<<dim3(D / 32, (B_SZ * NA) / 32), 256>>>(W1, b1);
    wt_kernel<<<dim3(D / 32, D / 32), dim3(32, 8)>>>(W1);
    w2t_kernel<<<1, 512>>>(W2);

    cudaFuncSetAttribute(pair_kernel, cudaFuncAttributeMaxDynamicSharedMemorySize, SMEM_REQ);
    pair_kernel<<<dim3(NBLK, 1, B_SZ), 256, SMEM_REQ>>>(b2, msk, out);
}

// round 7
// speedup vs baseline: 11.1705x; 1.0425x over previous
#include <cuda_runtime.h>
#include <cuda_bf16.h>
#include <cstdint>

#define D 512
#define NA 256
#define B_SZ 2
#define T_SEQ 1024
#define NB 7
#define MASK_FILL -10000.0f

#define TI 8
#define TJ 16
#define NBLK 272   // triangular blocks per batch

// smem layout (bytes). H overlays B buffer 0.
#define AP_B   1040              // A pitch: 520 bf16
#define BP_B   272               // B slab pitch: 136 bf16 (128 + 8 pad)
#define HP_B   272
#define WP_B   1040
#define OFF_A  0                 // 128 x 1040 = 133120
#define OFF_B  133120            // 2 x 34816
#define BBUF   34816
#define OFF_H  OFF_B             // overlays B buffer 0
#define OFF_W2T 202752           // 8 x 1040 = 8320
#define SMEM_REQ 211072

__device__ float g_A[B_SZ * NA * D];
__device__ float g_S[B_SZ * NA * D];
__device__ __nv_bfloat16 g_Wt[D * D];       // W1b^T: [n][k]
__device__ __nv_bfloat16 g_W2t[8 * D];      // W2^T padded: [c][k]

__device__ __forceinline__ uint32_t smem_u32(const void* p) {
    uint32_t a;
    asm("{ .reg .u64 t; cvta.to.shared.u64 t, %1; cvt.u32.u64 %0, t; }" : "=r"(a) : "l"(p));
    return a;
}
__device__ __forceinline__ uint32_t pack_bf16x2(float lo, float hi) {
    uint32_t r;
    asm("cvt.rn.bf16x2.f32 %0, %1, %2;" : "=r"(r) : "f"(hi), "f"(lo));
    return r;
}
// tanh-form GELU: g = x * u/(u+1), u = exp(1.5957691*x + 0.0713548*x^3).
// |g - gelu_exact| <= ~3e-4 — far inside the rel_err budget.
__device__ __forceinline__ float gelu_fast(float x) {
    float t = x * x;
    float c = fmaf(0.0713548162726f, t, 1.59576912161f);
    float u = __expf(x * c);
    return x - __fdividef(x, u + 1.f);
}

#define LDSM4(r, addr) \
    asm volatile("ldmatrix.sync.aligned.m8n8.x4.shared.b16 {%0,%1,%2,%3}, [%4];" \
        : "=r"((r)[0]), "=r"((r)[1]), "=r"((r)[2]), "=r"((r)[3]) : "r"(addr))
#define LDSM2(r0, r1, addr) \
    asm volatile("ldmatrix.sync.aligned.m8n8.x2.shared.b16 {%0,%1}, [%2];" \
        : "=r"(r0), "=r"(r1) : "r"(addr))
#define MMA16816(d, a, b0_, b1_) \
    asm volatile("mma.sync.aligned.m16n8k16.row.col.f32.bf16.bf16.f32 " \
        "{%0,%1,%2,%3}, {%4,%5,%6,%7}, {%8,%9}, {%0,%1,%2,%3};" \
        : "+f"((d)[0]), "+f"((d)[1]), "+f"((d)[2]), "+f"((d)[3]) \
        : "r"((a)[0]), "r"((a)[1]), "r"((a)[2]), "r"((a)[3]), "r"(b0_), "r"(b1_))
#define CP16(dst, src)  asm volatile("cp.async.cg.shared.global [%0], [%1], 16;" :: "r"(dst), "l"(src))
#define CP_COMMIT()     asm volatile("cp.async.commit_group;" ::: "memory")
#define CP_WAIT1()      asm volatile("cp.async.wait_group 1;" ::: "memory")
#define CP_WAIT0()      asm volatile("cp.async.wait_group 0;" ::: "memory")

// ---------------- prep 1: gather ----------------
__global__ void gather_kernel(const float* __restrict__ hs, const int* __restrict__ idx) {
    int r = blockIdx.x;
    int b = r / NA, n = r % NA;
    int t = idx[b * NA + n];
    t = t < 0 ? 0 : (t > T_SEQ - 1 ? T_SEQ - 1 : t);
    const float4* src = (const float4*)(hs + ((size_t)b * T_SEQ + t) * D);
    float4* dst = (float4*)(g_A + (size_t)r * D);
    for (int k = threadIdx.x; k < D / 4; k += blockDim.x) dst[k] = src[k];
}

// ---------------- prep 2: fused S-GEMM + W1b^T + W2^T ----------------
__global__ void prep2_kernel(const float* __restrict__ W1, const float* __restrict__ b1,
                             const float* __restrict__ W2) {
    __shared__ float sh[2304];
    const int tid = threadIdx.x;
    const int blk = blockIdx.x;
    if (blk < 256) {
        // S = A @ W1a + 0.5*b1 : 32x32 tile, 4 outputs/thread
        float (*sA)[33] = (float (*)[33])sh;            // 32*33 = 1056
        float (*sB)[36] = (float (*)[36])(sh + 1056);   // 32*36 = 1152
        const int r = tid >> 3;
        const int cq = (tid & 7) * 4;
        const int rowBase = (blk >> 4) * 32;
        const int colBase = (blk & 15) * 32;
        float4 acc = make_float4(0.f, 0.f, 0.f, 0.f);
        for (int k0 = 0; k0 < D; k0 += 32) {
            float4 av = *(const float4*)(g_A + (size_t)(rowBase + r) * D + k0 + cq);
            sA[r][cq] = av.x; sA[r][cq + 1] = av.y; sA[r][cq + 2] = av.z; sA[r][cq + 3] = av.w;
            *(float4*)(&sB[r][cq]) = *(const float4*)(W1 + (size_t)(k0 + r) * D + colBase + cq);
            __syncthreads();
#pragma unroll
            for (int k = 0; k < 32; k++) {
                float a = sA[r][k];
                float4 bv = *(float4*)(&sB[k][cq]);
                acc.x += a * bv.x; acc.y += a * bv.y; acc.z += a * bv.z; acc.w += a * bv.w;
            }
            __syncthreads();
        }
        float4 bb = *(const float4*)(b1 + colBase + cq);
        acc.x += 0.5f * bb.x; acc.y += 0.5f * bb.y; acc.z += 0.5f * bb.z; acc.w += 0.5f * bb.w;
        *(float4*)(g_S + (size_t)(rowBase + r) * D + colBase + cq) = acc;
    } else if (blk < 512) {
        // W1b transpose -> bf16
        float (*t)[33] = (float (*)[33])sh;
        const int q2 = blk - 256;
        const int n0 = (q2 & 15) * 32, k0 = (q2 >> 4) * 32;
        const int tx = tid & 31, ty = tid >> 5;   // 32 x 8
#pragma unroll
        for (int q = 0; q < 4; q++)
            t[ty + 8 * q][tx] = W1[(size_t)(D + k0 + ty + 8 * q) * D + n0 + tx];
        __syncthreads();
#pragma unroll
        for (int q = 0; q < 4; q++)
            g_Wt[(size_t)(n0 + ty + 8 * q) * D + k0 + tx] = __float2bfloat16(t[tx][ty + 8 * q]);
    } else {
        // W2 transpose (padded to 8 cols)
        for (int k = tid; k < D; k += 256)
#pragma unroll
            for (int c = 0; c < 8; c++)
                g_W2t[c * D + k] = (c < NB) ? __float2bfloat16(W2[(size_t)k * NB + c])
                                            : __float2bfloat16(0.f);
    }
}

// ---------------- main pairwise kernel (triangular, 128-k slabs) ----------------
__global__ void __launch_bounds__(256, 1)
pair_kernel(const float* __restrict__ b2, const int* __restrict__ mask,
            float* __restrict__ out) {
    extern __shared__ __align__(1024) char sm[];
    const uint32_t smb = smem_u32(sm);

    const int tid  = threadIdx.x;
    const int wid  = tid >> 5;
    const int lane = tid & 31;
    const int wm = wid >> 2;
    const int wn = wid & 3;
    const int gid = lane >> 2;
    const int tig = lane & 3;

    const int b = blockIdx.z;
    const int id = blockIdx.x;
    int bj = (int)((sqrtf(4.f * (float)id + 1.f) - 1.f) * 0.5f);
    while ((bj + 1) * (bj + 2) <= id) bj++;
    while (bj * (bj + 1) > id) bj--;
    const int bi = id - bj * (bj + 1);
    const int iBase = bi * TI;
    const int jBase = bj * TJ;

    // ---- build A = |a_i - a_j| bf16 into smem [128][520] ----
    {
        const float* Ai = g_A + (size_t)(b * NA + iBase) * D;
        const float* Aj = g_A + (size_t)(b * NA + jBase) * D;
#pragma unroll 4
        for (int it = 0; it < 128; it++) {
            int idx = tid + it * 256;
            int p = idx >> 8, kp = idx & 255;
            float2 a = __ldg((const float2*)(Ai + (size_t)(p >> 4) * D + kp * 2));
            float2 c = __ldg((const float2*)(Aj + (size_t)(p & 15) * D + kp * 2));
            *(uint32_t*)(sm + OFF_A + p * AP_B + kp * 4) =
                pack_bf16x2(fabsf(a.x - c.x), fabsf(a.y - c.y));
        }
    }
    // ---- W2t -> smem [8][520] ----
#pragma unroll
    for (int q = 0; q < 8; q++) {
        int idq = tid + q * 256;
        int c = idq >> 8, k2 = idq & 255;
        *(uint32_t*)(sm + OFF_W2T + c * WP_B + k2 * 4) =
            *(const uint32_t*)((const char*)g_W2t + ((size_t)c * D + k2 * 2) * 2);
    }
    __syncthreads();

    float la[4] = {0.f, 0.f, 0.f, 0.f};

    for (int chunk = 0; chunk < 4; chunk++) {
        float acc[4][4][4];
#pragma unroll
        for (int mt = 0; mt < 4; mt++)
#pragma unroll
            for (int nt = 0; nt < 4; nt++)
#pragma unroll
                for (int r = 0; r < 4; r++) acc[mt][nt][r] = 0.f;

        // preload slab 0 -> buf0 (buf0 free: prior h reads fenced by trailing sync)
        {
            const __nv_bfloat16* src = g_Wt + ((size_t)(chunk * 128) << 9);
#pragma unroll
            for (int q = 0; q < 8; q++) {
                int idq = tid + q * 256;
                int n = idq >> 4, c16 = idq & 15;
                CP16(smb + OFF_B + n * BP_B + c16 * 16, src + (size_t)n * D + c16 * 8);
            }
            CP_COMMIT();
        }

        for (int ks = 0; ks < 4; ks++) {
            if (ks < 3) {
                const __nv_bfloat16* src = g_Wt + ((size_t)(chunk * 128) << 9) + (ks + 1) * 128;
                uint32_t dbase = smb + OFF_B + ((ks + 1) & 1) * BBUF;
#pragma unroll
                for (int q = 0; q < 8; q++) {
                    int idq = tid + q * 256;
                    int n = idq >> 4, c16 = idq & 15;
                    CP16(dbase + n * BP_B + c16 * 16, src + (size_t)n * D + c16 * 8);
                }
                CP_COMMIT();
                CP_WAIT1();
            } else {
                CP_WAIT0();
            }
            __syncthreads();                      // slab ks visible

            const uint32_t bbase = smb + OFF_B + (ks & 1) * BBUF;
#pragma unroll
            for (int kk = 0; kk < 8; kk++) {
                const int kg = ks * 128 + kk * 16;
                uint32_t af[4][4];
#pragma unroll
                for (int mt = 0; mt < 4; mt++) {
                    uint32_t addr = smb + OFF_A
                        + (uint32_t)(wm * 64 + mt * 16 + (lane & 15)) * AP_B
                        + (uint32_t)(kg + (lane >> 4) * 8) * 2;
                    LDSM4(af[mt], addr);
                }
#pragma unroll
                for (int bt = 0; bt < 2; bt++) {
                    uint32_t addr = bbase
                        + (uint32_t)(wn * 32 + bt * 16 + (lane & 15)) * BP_B
                        + (uint32_t)(kk * 32 + (lane >> 4) * 16);
                    uint32_t rr[4];
                    LDSM4(rr, addr);
#pragma unroll
                    for (int mt = 0; mt < 4; mt++) {
                        MMA16816(acc[mt][bt * 2 + 0], af[mt], rr[0], rr[2]);
                        MMA16816(acc[mt][bt * 2 + 1], af[mt], rr[1], rr[3]);
                    }
                }
            }
            __syncthreads();                      // reads of this slab done
        }

        // ---- epilogue: + S_i + S_j, GELU, h -> smem (overlays buf0) ----
        const float* Sb = g_S + ((size_t)b * NA) * D + chunk * 128;
#pragma unroll
        for (int nt = 0; nt < 4; nt++) {
            const int cl = wn * 32 + nt * 8 + tig * 2;
            float2 sj0 = __ldg((const float2*)(Sb + (size_t)(jBase + gid) * D + cl));
            float2 sj8 = __ldg((const float2*)(Sb + (size_t)(jBase + gid + 8) * D + cl));
#pragma unroll
            for (int mt = 0; mt < 4; mt++) {
                float2 si = __ldg((const float2*)(Sb + (size_t)(iBase + wm * 4 + mt) * D + cl));
                float v0 = acc[mt][nt][0] + si.x + sj0.x;
                float v1 = acc[mt][nt][1] + si.y + sj0.y;
                float v2 = acc[mt][nt][2] + si.x + sj8.x;
                float v3 = acc[mt][nt][3] + si.y + sj8.y;
                uint32_t h01 = pack_bf16x2(gelu_fast(v0), gelu_fast(v1));
                uint32_t h23 = pack_bf16x2(gelu_fast(v2), gelu_fast(v3));
                const int p0 = wm * 64 + mt * 16 + gid;
                *(uint32_t*)(sm + OFF_H + p0 * HP_B + cl * 2) = h01;
                *(uint32_t*)(sm + OFF_H + (p0 + 8) * HP_B + cl * 2) = h23;
            }
        }
        __syncthreads();

        // ---- logits mma: h[16 pairs][128] x W2t ----
#pragma unroll
        for (int kk = 0; kk < 8; kk++) {
            uint32_t a[4];
            uint32_t aaddr = smb + OFF_H
                + (uint32_t)(wid * 16 + (lane & 15)) * HP_B
                + (uint32_t)(kk * 16 + (lane >> 4) * 8) * 2;
            LDSM4(a, aaddr);
            uint32_t b0, b1;
            uint32_t baddr = smb + OFF_W2T
                + (uint32_t)(lane & 7) * WP_B
                + (uint32_t)(chunk * 128 + kk * 16 + ((lane >> 3) & 1) * 8) * 2;
            LDSM2(b0, b1, baddr);
            MMA16816(la, a, b0, b1);
        }
        __syncthreads();                          // h reads done before next slab0 cp
    }

    // ---- store with mirror ----
    const int c0 = tig * 2, c1 = c0 + 1;
    const float bias0 = __ldg(b2 + c0);
    const float bias1 = (c1 < NB) ? __ldg(b2 + c1) : 0.f;
    float* ob = out + (size_t)b * NB * NA * NA;
#pragma unroll
    for (int h = 0; h < 2; h++) {
        const int p = wid * 16 + gid + h * 8;
        const int i = iBase + (p >> 4);
        const int j = jBase + (p & 15);
        if (i > j) continue;
        if (i == j) {
            ob[(size_t)c0 * NA * NA + i * NA + j] = MASK_FILL;
            if (c1 < NB) ob[(size_t)c1 * NA * NA + i * NA + j] = MASK_FILL;
            continue;
        }
        const bool valid = (__ldg(mask + b * NA + i) != 0) &&
                           (__ldg(mask + b * NA + j) != 0);
        float v0 = valid ? (la[h * 2 + 0] + bias0) : MASK_FILL;
        ob[(size_t)c0 * NA * NA + i * NA + j] = v0;
        ob[(size_t)c0 * NA * NA + j * NA + i] = v0;
        if (c1 < NB) {
            float v1 = valid ? (la[h * 2 + 1] + bias1) : MASK_FILL;
            ob[(size_t)c1 * NA * NA + i * NA + j] = v1;
            ob[(size_t)c1 * NA * NA + j * NA + i] = v1;
        }
    }
}

extern "C" void kernel_launch(void* const* d_in, const int* in_sizes, int n_in,
                              void* d_out, int out_size) {
    (void)in_sizes; (void)n_in; (void)out_size;
    const float* hs = (const float*)d_in[0];
    const float* W1 = (const float*)d_in[1];
    const float* b1 = (const float*)d_in[2];
    const float* W2 = (const float*)d_in[3];
    const float* b2 = (const float*)d_in[4];
    const int* idx  = (const int*)d_in[5];
    const int* msk  = (const int*)d_in[6];
    float* out = (float*)d_out;

    gather_kernel<<<B_SZ * NA, 128>>>(hs, idx);
    prep2_kernel<<<513, 256>>>(W1, b1, W2);

    cudaFuncSetAttribute(pair_kernel, cudaFuncAttributeMaxDynamicSharedMemorySize, SMEM_REQ);
    pair_kernel<<<dim3(NBLK, 1, B_SZ), 256, SMEM_REQ>>>(b2, msk, out);
}

// round 8
// speedup vs baseline: 11.7385x; 1.0508x over previous
#include <cuda_runtime.h>
#include <cuda_bf16.h>
#include <cstdint>

#define D 512
#define NA 256
#define B_SZ 2
#define T_SEQ 1024
#define NB 7
#define MASK_FILL -10000.0f

#define TI 8
#define TJ 16
#define NBLK 272   // triangular blocks per batch

// smem layout (bytes). H overlays B buffer 0.
#define AP_B   1040              // A pitch: 520 bf16
#define BP_B   272               // B slab pitch: 136 bf16
#define HP_B   272
#define WP_B   1040
#define OFF_A  0                 // 128 x 1040 = 133120
#define OFF_B  133120            // 2 x 34816
#define BBUF   34816
#define OFF_H  OFF_B             // overlays B buffer 0
#define OFF_W2T 202752           // 8 x 1040 = 8320
#define SMEM_REQ 211072

__device__ float g_A[B_SZ * NA * D];
__device__ float g_S[B_SZ * NA * D];
__device__ __nv_bfloat16 g_Wt[D * D];       // W1b^T: [n][k]
__device__ __nv_bfloat16 g_W2t[8 * D];      // W2^T padded: [c][k]

__device__ __forceinline__ uint32_t smem_u32(const void* p) {
    uint32_t a;
    asm("{ .reg .u64 t; cvta.to.shared.u64 t, %1; cvt.u32.u64 %0, t; }" : "=r"(a) : "l"(p));
    return a;
}
__device__ __forceinline__ uint32_t pack_bf16x2(float lo, float hi) {
    uint32_t r;
    asm("cvt.rn.bf16x2.f32 %0, %1, %2;" : "=r"(r) : "f"(hi), "f"(lo));
    return r;
}
// tanh-form GELU (|err| <= ~3e-4, far inside budget)
__device__ __forceinline__ float gelu_fast(float x) {
    float t = x * x;
    float c = fmaf(0.0713548162726f, t, 1.59576912161f);
    float u = __expf(x * c);
    return x - __fdividef(x, u + 1.f);
}

#define LDSM4(r, addr) \
    asm volatile("ldmatrix.sync.aligned.m8n8.x4.shared.b16 {%0,%1,%2,%3}, [%4];" \
        : "=r"((r)[0]), "=r"((r)[1]), "=r"((r)[2]), "=r"((r)[3]) : "r"(addr))
#define LDSM2(r0, r1, addr) \
    asm volatile("ldmatrix.sync.aligned.m8n8.x2.shared.b16 {%0,%1}, [%2];" \
        : "=r"(r0), "=r"(r1) : "r"(addr))
#define MMA16816(d, a, b0_, b1_) \
    asm volatile("mma.sync.aligned.m16n8k16.row.col.f32.bf16.bf16.f32 " \
        "{%0,%1,%2,%3}, {%4,%5,%6,%7}, {%8,%9}, {%0,%1,%2,%3};" \
        : "+f"((d)[0]), "+f"((d)[1]), "+f"((d)[2]), "+f"((d)[3]) \
        : "r"((a)[0]), "r"((a)[1]), "r"((a)[2]), "r"((a)[3]), "r"(b0_), "r"(b1_))
#define CP16(dst, src)  asm volatile("cp.async.cg.shared.global [%0], [%1], 16;" :: "r"(dst), "l"(src))
#define CP_COMMIT()     asm volatile("cp.async.commit_group;" ::: "memory")
#define CP_WAIT1()      asm volatile("cp.async.wait_group 1;" ::: "memory")
#define CP_WAIT0()      asm volatile("cp.async.wait_group 0;" ::: "memory")

// ---------------- prep 1: gather ----------------
__global__ void gather_kernel(const float* __restrict__ hs, const int* __restrict__ idx) {
    int r = blockIdx.x;
    int b = r / NA, n = r % NA;
    int t = idx[b * NA + n];
    t = t < 0 ? 0 : (t > T_SEQ - 1 ? T_SEQ - 1 : t);
    const float4* src = (const float4*)(hs + ((size_t)b * T_SEQ + t) * D);
    float4* dst = (float4*)(g_A + (size_t)r * D);
    for (int k = threadIdx.x; k < D / 4; k += blockDim.x) dst[k] = src[k];
}

// ---------------- prep 2: fused S-GEMM + W1b^T + W2^T ----------------
__global__ void prep2_kernel(const float* __restrict__ W1, const float* __restrict__ b1,
                             const float* __restrict__ W2) {
    __shared__ float sh[2304];
    const int tid = threadIdx.x;
    const int blk = blockIdx.x;
    if (blk < 256) {
        float (*sA)[33] = (float (*)[33])sh;
        float (*sB)[36] = (float (*)[36])(sh + 1056);
        const int r = tid >> 3;
        const int cq = (tid & 7) * 4;
        const int rowBase = (blk >> 4) * 32;
        const int colBase = (blk & 15) * 32;
        float4 acc = make_float4(0.f, 0.f, 0.f, 0.f);
        for (int k0 = 0; k0 < D; k0 += 32) {
            float4 av = *(const float4*)(g_A + (size_t)(rowBase + r) * D + k0 + cq);
            sA[r][cq] = av.x; sA[r][cq + 1] = av.y; sA[r][cq + 2] = av.z; sA[r][cq + 3] = av.w;
            *(float4*)(&sB[r][cq]) = *(const float4*)(W1 + (size_t)(k0 + r) * D + colBase + cq);
            __syncthreads();
#pragma unroll
            for (int k = 0; k < 32; k++) {
                float a = sA[r][k];
                float4 bv = *(float4*)(&sB[k][cq]);
                acc.x += a * bv.x; acc.y += a * bv.y; acc.z += a * bv.z; acc.w += a * bv.w;
            }
            __syncthreads();
        }
        float4 bb = *(const float4*)(b1 + colBase + cq);
        acc.x += 0.5f * bb.x; acc.y += 0.5f * bb.y; acc.z += 0.5f * bb.z; acc.w += 0.5f * bb.w;
        *(float4*)(g_S + (size_t)(rowBase + r) * D + colBase + cq) = acc;
    } else if (blk < 512) {
        float (*t)[33] = (float (*)[33])sh;
        const int q2 = blk - 256;
        const int n0 = (q2 & 15) * 32, k0 = (q2 >> 4) * 32;
        const int tx = tid & 31, ty = tid >> 5;
#pragma unroll
        for (int q = 0; q < 4; q++)
            t[ty + 8 * q][tx] = W1[(size_t)(D + k0 + ty + 8 * q) * D + n0 + tx];
        __syncthreads();
#pragma unroll
        for (int q = 0; q < 4; q++)
            g_Wt[(size_t)(n0 + ty + 8 * q) * D + k0 + tx] = __float2bfloat16(t[tx][ty + 8 * q]);
    } else {
        for (int k = tid; k < D; k += 256)
#pragma unroll
            for (int c = 0; c < 8; c++)
                g_W2t[c * D + k] = (c < NB) ? __float2bfloat16(W2[(size_t)k * NB + c])
                                            : __float2bfloat16(0.f);
    }
}

// fragment load helpers (A: 4 x LDSM4, B: 2 x LDSM4)
#define LOAD_AFRAG(af, kg)                                                    \
    do {                                                                      \
        _Pragma("unroll")                                                     \
        for (int mt = 0; mt < 4; mt++) {                                      \
            uint32_t addr = smb + OFF_A                                       \
                + (uint32_t)(wm * 64 + mt * 16 + (lane & 15)) * AP_B          \
                + (uint32_t)((kg) + (lane >> 4) * 8) * 2;                     \
            LDSM4((af)[mt], addr);                                            \
        }                                                                     \
    } while (0)
#define LOAD_BFRAG(bb, bbase, kk)                                             \
    do {                                                                      \
        _Pragma("unroll")                                                     \
        for (int bt = 0; bt < 2; bt++) {                                      \
            uint32_t addr = (bbase)                                           \
                + (uint32_t)(wn * 32 + bt * 16 + (lane & 15)) * BP_B          \
                + (uint32_t)((kk) * 32 + (lane >> 4) * 16);                   \
            LDSM4((bb)[bt], addr);                                            \
        }                                                                     \
    } while (0)

// ---------------- main pairwise kernel ----------------
__global__ void __launch_bounds__(256, 1)
pair_kernel(const float* __restrict__ b2, const int* __restrict__ mask,
            float* __restrict__ out) {
    extern __shared__ __align__(1024) char sm[];
    const uint32_t smb = smem_u32(sm);

    const int tid  = threadIdx.x;
    const int wid  = tid >> 5;
    const int lane = tid & 31;
    const int wm = wid >> 2;
    const int wn = wid & 3;
    const int gid = lane >> 2;
    const int tig = lane & 3;

    const int b = blockIdx.z;
    const int id = blockIdx.x;
    int bj = (int)((sqrtf(4.f * (float)id + 1.f) - 1.f) * 0.5f);
    while ((bj + 1) * (bj + 2) <= id) bj++;
    while (bj * (bj + 1) > id) bj--;
    const int bi = id - bj * (bj + 1);
    const int iBase = bi * TI;
    const int jBase = bj * TJ;

    // ---- build A = |a_i - a_j| bf16 into smem [128][520] (float4 path) ----
    {
        const float* Ai = g_A + (size_t)(b * NA + iBase) * D;
        const float* Aj = g_A + (size_t)(b * NA + jBase) * D;
#pragma unroll 4
        for (int it = 0; it < 64; it++) {
            int idx = tid + it * 256;          // 0..16383, each = 4 k values
            int p = idx >> 7, kq = idx & 127;  // k = 4*kq
            float4 a = __ldg((const float4*)(Ai + (size_t)(p >> 4) * D + kq * 4));
            float4 c = __ldg((const float4*)(Aj + (size_t)(p & 15) * D + kq * 4));
            uint32_t lo = pack_bf16x2(fabsf(a.x - c.x), fabsf(a.y - c.y));
            uint32_t hi = pack_bf16x2(fabsf(a.z - c.z), fabsf(a.w - c.w));
            *(uint2*)(sm + OFF_A + p * AP_B + kq * 8) = make_uint2(lo, hi);
        }
    }
    // ---- W2t -> smem [8][520] ----
#pragma unroll
    for (int q = 0; q < 8; q++) {
        int idq = tid + q * 256;
        int c = idq >> 8, k2 = idq & 255;
        *(uint32_t*)(sm + OFF_W2T + c * WP_B + k2 * 4) =
            *(const uint32_t*)((const char*)g_W2t + ((size_t)c * D + k2 * 2) * 2);
    }
    __syncthreads();

    float la[4] = {0.f, 0.f, 0.f, 0.f};

    for (int chunk = 0; chunk < 4; chunk++) {
        float acc[4][4][4];
#pragma unroll
        for (int mt = 0; mt < 4; mt++)
#pragma unroll
            for (int nt = 0; nt < 4; nt++)
#pragma unroll
                for (int r = 0; r < 4; r++) acc[mt][nt][r] = 0.f;

        {
            const __nv_bfloat16* src = g_Wt + ((size_t)(chunk * 128) << 9);
#pragma unroll
            for (int q = 0; q < 8; q++) {
                int idq = tid + q * 256;
                int n = idq >> 4, c16 = idq & 15;
                CP16(smb + OFF_B + n * BP_B + c16 * 16, src + (size_t)n * D + c16 * 8);
            }
            CP_COMMIT();
        }

        for (int ks = 0; ks < 4; ks++) {
            if (ks < 3) {
                const __nv_bfloat16* src = g_Wt + ((size_t)(chunk * 128) << 9) + (ks + 1) * 128;
                uint32_t dbase = smb + OFF_B + ((ks + 1) & 1) * BBUF;
#pragma unroll
                for (int q = 0; q < 8; q++) {
                    int idq = tid + q * 256;
                    int n = idq >> 4, c16 = idq & 15;
                    CP16(dbase + n * BP_B + c16 * 16, src + (size_t)n * D + c16 * 8);
                }
                CP_COMMIT();
                CP_WAIT1();
            } else {
                CP_WAIT0();
            }
            __syncthreads();                      // slab ks visible

            const uint32_t bbase = smb + OFF_B + (ks & 1) * BBUF;

            // software-pipelined fragment loads: prefetch kk+1 during kk's MMAs
            uint32_t af[2][4][4];
            uint32_t bbf[2][2][4];
            LOAD_AFRAG(af[0], ks * 128);
            LOAD_BFRAG(bbf[0], bbase, 0);
#pragma unroll
            for (int kk = 0; kk < 8; kk++) {
                const int cur = kk & 1, nxt = cur ^ 1;
                if (kk < 7) {
                    LOAD_AFRAG(af[nxt], ks * 128 + (kk + 1) * 16);
                    LOAD_BFRAG(bbf[nxt], bbase, kk + 1);
                }
#pragma unroll
                for (int bt = 0; bt < 2; bt++) {
#pragma unroll
                    for (int mt = 0; mt < 4; mt++) {
                        MMA16816(acc[mt][bt * 2 + 0], af[cur][mt], bbf[cur][bt][0], bbf[cur][bt][2]);
                        MMA16816(acc[mt][bt * 2 + 1], af[cur][mt], bbf[cur][bt][1], bbf[cur][bt][3]);
                    }
                }
            }
            __syncthreads();                      // reads of this slab done
        }

        // ---- epilogue: + S_i + S_j, GELU, h -> smem (overlays buf0) ----
        const float* Sb = g_S + ((size_t)b * NA) * D + chunk * 128;
#pragma unroll
        for (int nt = 0; nt < 4; nt++) {
            const int cl = wn * 32 + nt * 8 + tig * 2;
            float2 sj0 = __ldg((const float2*)(Sb + (size_t)(jBase + gid) * D + cl));
            float2 sj8 = __ldg((const float2*)(Sb + (size_t)(jBase + gid + 8) * D + cl));
#pragma unroll
            for (int mt = 0; mt < 4; mt++) {
                float2 si = __ldg((const float2*)(Sb + (size_t)(iBase + wm * 4 + mt) * D + cl));
                float v0 = acc[mt][nt][0] + si.x + sj0.x;
                float v1 = acc[mt][nt][1] + si.y + sj0.y;
                float v2 = acc[mt][nt][2] + si.x + sj8.x;
                float v3 = acc[mt][nt][3] + si.y + sj8.y;
                uint32_t h01 = pack_bf16x2(gelu_fast(v0), gelu_fast(v1));
                uint32_t h23 = pack_bf16x2(gelu_fast(v2), gelu_fast(v3));
                const int p0 = wm * 64 + mt * 16 + gid;
                *(uint32_t*)(sm + OFF_H + p0 * HP_B + cl * 2) = h01;
                *(uint32_t*)(sm + OFF_H + (p0 + 8) * HP_B + cl * 2) = h23;
            }
        }
        __syncthreads();

        // ---- logits mma: h[16 pairs][128] x W2t ----
#pragma unroll
        for (int kk = 0; kk < 8; kk++) {
            uint32_t a[4];
            uint32_t aaddr = smb + OFF_H
                + (uint32_t)(wid * 16 + (lane & 15)) * HP_B
                + (uint32_t)(kk * 16 + (lane >> 4) * 8) * 2;
            LDSM4(a, aaddr);
            uint32_t b0, b1;
            uint32_t baddr = smb + OFF_W2T
                + (uint32_t)(lane & 7) * WP_B
                + (uint32_t)(chunk * 128 + kk * 16 + ((lane >> 3) & 1) * 8) * 2;
            LDSM2(b0, b1, baddr);
            MMA16816(la, a, b0, b1);
        }
        __syncthreads();                          // h reads done before next slab0 cp
    }

    // ---- store with mirror ----
    const int c0 = tig * 2, c1 = c0 + 1;
    const float bias0 = __ldg(b2 + c0);
    const float bias1 = (c1 < NB) ? __ldg(b2 + c1) : 0.f;
    float* ob = out + (size_t)b * NB * NA * NA;
#pragma unroll
    for (int h = 0; h < 2; h++) {
        const int p = wid * 16 + gid + h * 8;
        const int i = iBase + (p >> 4);
        const int j = jBase + (p & 15);
        if (i > j) continue;
        if (i == j) {
            ob[(size_t)c0 * NA * NA + i * NA + j] = MASK_FILL;
            if (c1 < NB) ob[(size_t)c1 * NA * NA + i * NA + j] = MASK_FILL;
            continue;
        }
        const bool valid = (__ldg(mask + b * NA + i) != 0) &&
                           (__ldg(mask + b * NA + j) != 0);
        float v0 = valid ? (la[h * 2 + 0] + bias0) : MASK_FILL;
        ob[(size_t)c0 * NA * NA + i * NA + j] = v0;
        ob[(size_t)c0 * NA * NA + j * NA + i] = v0;
        if (c1 < NB) {
            float v1 = valid ? (la[h * 2 + 1] + bias1) : MASK_FILL;
            ob[(size_t)c1 * NA * NA + i * NA + j] = v1;
            ob[(size_t)c1 * NA * NA + j * NA + i] = v1;
        }
    }
}

extern "C" void kernel_launch(void* const* d_in, const int* in_sizes, int n_in,
                              void* d_out, int out_size) {
    (void)in_sizes; (void)n_in; (void)out_size;
    const float* hs = (const float*)d_in[0];
    const float* W1 = (const float*)d_in[1];
    const float* b1 = (const float*)d_in[2];
    const float* W2 = (const float*)d_in[3];
    const float* b2 = (const float*)d_in[4];
    const int* idx  = (const int*)d_in[5];
    const int* msk  = (const int*)d_in[6];
    float* out = (float*)d_out;

    gather_kernel<<<B_SZ * NA, 128>>>(hs, idx);
    prep2_kernel<<<513, 256>>>(W1, b1, W2);

    cudaFuncSetAttribute(pair_kernel, cudaFuncAttributeMaxDynamicSharedMemorySize, SMEM_REQ);
    pair_kernel<<<dim3(NBLK, 1, B_SZ), 256, SMEM_REQ>>>(b2, msk, out);
}

// round 9
// speedup vs baseline: 13.8712x; 1.1817x over previous
#include <cuda_runtime.h>
#include <cuda_bf16.h>
#include <cstdint>

#define D 512
#define NA 256
#define B_SZ 2
#define T_SEQ 1024
#define NB 7
#define MASK_FILL -10000.0f

#define TI 8
#define TJ 16
#define NBLK 272   // triangular blocks per batch

// fp8 smem layout (bytes)
#define AP_B   528               // A pitch: 512 fp8 + 16 pad
#define BP_B   144               // B slab pitch: 128 fp8 + 16 pad
#define HP_B   144               // h pitch (fp8)
#define WP_B   528               // W2t pitch (fp8)
#define OFF_A  0                 // 128 x 528 = 67584
#define OFF_B  67584             // 2 x 18432 = 36864
#define BBUF   18432
#define OFF_H  OFF_B             // h overlays B buffer 0 (18432 fits 2 bufs)
#define OFF_W2T 104448           // 8 x 528 = 4224
#define SMEM_REQ 108672

#define WSCALE 16.0f             // W1b, W2, h pre-scale for e4m3 dynamic range

__device__ float g_A[B_SZ * NA * D];
__device__ float g_S[B_SZ * NA * D];
__device__ uint8_t g_W8t[D * D];     // e4m3(16 * W1b^T)[n][k]
__device__ uint8_t g_W28t[8 * D];    // e4m3(16 * W2^T)[c][k], c=7 zeros

__device__ __forceinline__ uint32_t smem_u32(const void* p) {
    uint32_t a;
    asm("{ .reg .u64 t; cvta.to.shared.u64 t, %1; cvt.u32.u64 %0, t; }" : "=r"(a) : "l"(p));
    return a;
}
__device__ __forceinline__ uint16_t pack_e4m3x2(float lo, float hi) {
    uint16_t r;
    asm("cvt.rn.satfinite.e4m3x2.f32 %0, %1, %2;" : "=h"(r) : "f"(hi), "f"(lo));
    return r;
}
__device__ __forceinline__ uint32_t pack_e4m3x4(float f0, float f1, float f2, float f3) {
    uint16_t lo = pack_e4m3x2(f0, f1);
    uint16_t hi = pack_e4m3x2(f2, f3);
    return (uint32_t)lo | ((uint32_t)hi << 16);
}
// tanh-form GELU (|err| <= ~3e-4)
__device__ __forceinline__ float gelu_fast(float x) {
    float t = x * x;
    float c = fmaf(0.0713548162726f, t, 1.59576912161f);
    float u = __expf(x * c);
    return x - __fdividef(x, u + 1.f);
}

#define LDSM4(r, addr) \
    asm volatile("ldmatrix.sync.aligned.m8n8.x4.shared.b16 {%0,%1,%2,%3}, [%4];" \
        : "=r"((r)[0]), "=r"((r)[1]), "=r"((r)[2]), "=r"((r)[3]) : "r"(addr))
#define LDSM2(r0, r1, addr) \
    asm volatile("ldmatrix.sync.aligned.m8n8.x2.shared.b16 {%0,%1}, [%2];" \
        : "=r"(r0), "=r"(r1) : "r"(addr))
// fp8 e4m3 MMA, K=32 per instruction (sm_89+ baseline ISA)
#define MMAFP8(d, a, b0_, b1_) \
    asm volatile("mma.sync.aligned.m16n8k32.row.col.f32.e4m3.e4m3.f32 " \
        "{%0,%1,%2,%3}, {%4,%5,%6,%7}, {%8,%9}, {%0,%1,%2,%3};" \
        : "+f"((d)[0]), "+f"((d)[1]), "+f"((d)[2]), "+f"((d)[3]) \
        : "r"((a)[0]), "r"((a)[1]), "r"((a)[2]), "r"((a)[3]), "r"(b0_), "r"(b1_))
#define CP16(dst, src)  asm volatile("cp.async.cg.shared.global [%0], [%1], 16;" :: "r"(dst), "l"(src))
#define CP_COMMIT()     asm volatile("cp.async.commit_group;" ::: "memory")
#define CP_WAIT1()      asm volatile("cp.async.wait_group 1;" ::: "memory")
#define CP_WAIT0()      asm volatile("cp.async.wait_group 0;" ::: "memory")

// ---------------- prep 1: gather ----------------
__global__ void gather_kernel(const float* __restrict__ hs, const int* __restrict__ idx) {
    int r = blockIdx.x;
    int b = r / NA, n = r % NA;
    int t = idx[b * NA + n];
    t = t < 0 ? 0 : (t > T_SEQ - 1 ? T_SEQ - 1 : t);
    const float4* src = (const float4*)(hs + ((size_t)b * T_SEQ + t) * D);
    float4* dst = (float4*)(g_A + (size_t)r * D);
    for (int k = threadIdx.x; k < D / 4; k += blockDim.x) dst[k] = src[k];
}

// ---------------- prep 2: fused S-GEMM + W1b^T(fp8) + W2^T(fp8) ----------------
__global__ void prep2_kernel(const float* __restrict__ W1, const float* __restrict__ b1,
                             const float* __restrict__ W2) {
    __shared__ float sh[2304];
    const int tid = threadIdx.x;
    const int blk = blockIdx.x;
    if (blk < 256) {
        float (*sA)[33] = (float (*)[33])sh;
        float (*sB)[36] = (float (*)[36])(sh + 1056);
        const int r = tid >> 3;
        const int cq = (tid & 7) * 4;
        const int rowBase = (blk >> 4) * 32;
        const int colBase = (blk & 15) * 32;
        float4 acc = make_float4(0.f, 0.f, 0.f, 0.f);
        for (int k0 = 0; k0 < D; k0 += 32) {
            float4 av = *(const float4*)(g_A + (size_t)(rowBase + r) * D + k0 + cq);
            sA[r][cq] = av.x; sA[r][cq + 1] = av.y; sA[r][cq + 2] = av.z; sA[r][cq + 3] = av.w;
            *(float4*)(&sB[r][cq]) = *(const float4*)(W1 + (size_t)(k0 + r) * D + colBase + cq);
            __syncthreads();
#pragma unroll
            for (int k = 0; k < 32; k++) {
                float a = sA[r][k];
                float4 bv = *(float4*)(&sB[k][cq]);
                acc.x += a * bv.x; acc.y += a * bv.y; acc.z += a * bv.z; acc.w += a * bv.w;
            }
            __syncthreads();
        }
        float4 bb = *(const float4*)(b1 + colBase + cq);
        acc.x += 0.5f * bb.x; acc.y += 0.5f * bb.y; acc.z += 0.5f * bb.z; acc.w += 0.5f * bb.w;
        *(float4*)(g_S + (size_t)(rowBase + r) * D + colBase + cq) = acc;
    } else if (blk < 512) {
        // W1b^T -> fp8 e4m3 scaled by 16
        float (*t)[33] = (float (*)[33])sh;   // t[k_local][n_local]
        const int q2 = blk - 256;
        const int n0 = (q2 & 15) * 32, k0 = (q2 >> 4) * 32;
        const int tx = tid & 31, ty = tid >> 5;
#pragma unroll
        for (int q = 0; q < 4; q++)
            t[ty + 8 * q][tx] = W1[(size_t)(D + k0 + ty + 8 * q) * D + n0 + tx];
        __syncthreads();
        const int nn = tid >> 3;          // 0..31
        const int kq = tid & 7;           // 0..7 -> k_local = kq*4
        uint32_t v = pack_e4m3x4(WSCALE * t[kq * 4 + 0][nn], WSCALE * t[kq * 4 + 1][nn],
                                 WSCALE * t[kq * 4 + 2][nn], WSCALE * t[kq * 4 + 3][nn]);
        *(uint32_t*)&g_W8t[(size_t)(n0 + nn) * D + k0 + kq * 4] = v;
    } else {
        // W2^T -> fp8 e4m3 scaled by 16 (8 rows, row 7 zero)
        if (tid < 128) {
            const int k4 = tid * 4;
#pragma unroll
            for (int c = 0; c < 8; c++) {
                float f0 = (c < NB) ? WSCALE * W2[(size_t)(k4 + 0) * NB + c] : 0.f;
                float f1 = (c < NB) ? WSCALE * W2[(size_t)(k4 + 1) * NB + c] : 0.f;
                float f2 = (c < NB) ? WSCALE * W2[(size_t)(k4 + 2) * NB + c] : 0.f;
                float f3 = (c < NB) ? WSCALE * W2[(size_t)(k4 + 3) * NB + c] : 0.f;
                *(uint32_t*)&g_W28t[c * D + k4] = pack_e4m3x4(f0, f1, f2, f3);
            }
        }
    }
}

// ---------------- main pairwise kernel (fp8, 2 CTAs/SM) ----------------
__global__ void __launch_bounds__(256, 2)
pair_kernel(const float* __restrict__ b2, const int* __restrict__ mask,
            float* __restrict__ out) {
    extern __shared__ __align__(1024) char sm[];
    const uint32_t smb = smem_u32(sm);

    const int tid  = threadIdx.x;
    const int wid  = tid >> 5;
    const int lane = tid & 31;
    const int wm = wid >> 2;
    const int wn = wid & 3;
    const int gid = lane >> 2;
    const int tig = lane & 3;

    const int b = blockIdx.z;
    const int id = blockIdx.x;
    int bj = (int)((sqrtf(4.f * (float)id + 1.f) - 1.f) * 0.5f);
    while ((bj + 1) * (bj + 2) <= id) bj++;
    while (bj * (bj + 1) > id) bj--;
    const int bi = id - bj * (bj + 1);
    const int iBase = bi * TI;
    const int jBase = bj * TJ;

    // ---- build A = e4m3(|a_i - a_j|) into smem [128][512+16] ----
    {
        const float* Ai = g_A + (size_t)(b * NA + iBase) * D;
        const float* Aj = g_A + (size_t)(b * NA + jBase) * D;
#pragma unroll 4
        for (int it = 0; it < 64; it++) {
            int idx = tid + it * 256;          // 0..16383, each = 4 k values
            int p = idx >> 7, kq = idx & 127;  // k = 4*kq
            float4 a = __ldg((const float4*)(Ai + (size_t)(p >> 4) * D + kq * 4));
            float4 c = __ldg((const float4*)(Aj + (size_t)(p & 15) * D + kq * 4));
            *(uint32_t*)(sm + OFF_A + p * AP_B + kq * 4) =
                pack_e4m3x4(fabsf(a.x - c.x), fabsf(a.y - c.y),
                            fabsf(a.z - c.z), fabsf(a.w - c.w));
        }
    }
    // ---- W2t(fp8) -> smem [8][528] ----
    if (tid < 128) {
        const int k4 = tid * 4;
#pragma unroll
        for (int c = 0; c < 8; c++)
            *(uint32_t*)(sm + OFF_W2T + c * WP_B + k4) = *(const uint32_t*)&g_W28t[c * D + k4];
    }
    __syncthreads();

    float la[4] = {0.f, 0.f, 0.f, 0.f};

    for (int chunk = 0; chunk < 4; chunk++) {
        float acc[4][4][4];
#pragma unroll
        for (int mt = 0; mt < 4; mt++)
#pragma unroll
            for (int nt = 0; nt < 4; nt++)
#pragma unroll
                for (int r = 0; r < 4; r++) acc[mt][nt][r] = 0.f;

        // preload slab 0 -> buf0 (prior h reads fenced by trailing sync)
        {
            const uint8_t* src = g_W8t + ((size_t)(chunk * 128) << 9);
#pragma unroll
            for (int q = 0; q < 4; q++) {
                int idq = tid + q * 256;
                int n = idq >> 3, c16 = idq & 7;
                CP16(smb + OFF_B + n * BP_B + c16 * 16, src + (size_t)n * D + c16 * 16);
            }
            CP_COMMIT();
        }

        for (int ks = 0; ks < 4; ks++) {
            if (ks < 3) {
                const uint8_t* src = g_W8t + ((size_t)(chunk * 128) << 9) + (ks + 1) * 128;
                uint32_t dbase = smb + OFF_B + ((ks + 1) & 1) * BBUF;
#pragma unroll
                for (int q = 0; q < 4; q++) {
                    int idq = tid + q * 256;
                    int n = idq >> 3, c16 = idq & 7;
                    CP16(dbase + n * BP_B + c16 * 16, src + (size_t)n * D + c16 * 16);
                }
                CP_COMMIT();
                CP_WAIT1();
            } else {
                CP_WAIT0();
            }
            __syncthreads();                      // slab ks visible

            const uint32_t bbase = smb + OFF_B + (ks & 1) * BBUF;
#pragma unroll
            for (int kk = 0; kk < 4; kk++) {      // k32 per step
                const int kgB = ks * 128 + kk * 32;   // byte col in A (fp8)
                uint32_t af[4][4];
#pragma unroll
                for (int mt = 0; mt < 4; mt++) {
                    uint32_t addr = smb + OFF_A
                        + (uint32_t)(wm * 64 + mt * 16 + (lane & 15)) * AP_B
                        + (uint32_t)(kgB + (lane >> 4) * 16);
                    LDSM4(af[mt], addr);
                }
#pragma unroll
                for (int bt = 0; bt < 2; bt++) {
                    uint32_t addr = bbase
                        + (uint32_t)(wn * 32 + bt * 16 + (lane & 15)) * BP_B
                        + (uint32_t)(kk * 32 + (lane >> 4) * 16);
                    uint32_t rr[4];
                    LDSM4(rr, addr);
#pragma unroll
                    for (int mt = 0; mt < 4; mt++) {
                        MMAFP8(acc[mt][bt * 2 + 0], af[mt], rr[0], rr[2]);
                        MMAFP8(acc[mt][bt * 2 + 1], af[mt], rr[1], rr[3]);
                    }
                }
            }
            __syncthreads();                      // reads of this slab done
        }

        // ---- epilogue: acc/16 + S_i + S_j, GELU, h(fp8 x16) -> smem (overlays buf0) ----
        const float* Sb = g_S + ((size_t)b * NA) * D + chunk * 128;
        const float inv16 = 1.f / WSCALE;
#pragma unroll
        for (int nt = 0; nt < 4; nt++) {
            const int cl = wn * 32 + nt * 8 + tig * 2;
            float2 sj0 = __ldg((const float2*)(Sb + (size_t)(jBase + gid) * D + cl));
            float2 sj8 = __ldg((const float2*)(Sb + (size_t)(jBase + gid + 8) * D + cl));
#pragma unroll
            for (int mt = 0; mt < 4; mt++) {
                float2 si = __ldg((const float2*)(Sb + (size_t)(iBase + wm * 4 + mt) * D + cl));
                float v0 = acc[mt][nt][0] * inv16 + si.x + sj0.x;
                float v1 = acc[mt][nt][1] * inv16 + si.y + sj0.y;
                float v2 = acc[mt][nt][2] * inv16 + si.x + sj8.x;
                float v3 = acc[mt][nt][3] * inv16 + si.y + sj8.y;
                uint16_t h01 = pack_e4m3x2(WSCALE * gelu_fast(v0), WSCALE * gelu_fast(v1));
                uint16_t h23 = pack_e4m3x2(WSCALE * gelu_fast(v2), WSCALE * gelu_fast(v3));
                const int p0 = wm * 64 + mt * 16 + gid;
                *(uint16_t*)(sm + OFF_H + p0 * HP_B + cl) = h01;
                *(uint16_t*)(sm + OFF_H + (p0 + 8) * HP_B + cl) = h23;
            }
        }
        __syncthreads();

        // ---- logits mma (fp8): h[16 pairs][128] x W2t ----
#pragma unroll
        for (int kk = 0; kk < 4; kk++) {
            uint32_t a[4];
            uint32_t aaddr = smb + OFF_H
                + (uint32_t)(wid * 16 + (lane & 15)) * HP_B
                + (uint32_t)(kk * 32 + (lane >> 4) * 16);
            LDSM4(a, aaddr);
            uint32_t b0, b1;
            uint32_t baddr = smb + OFF_W2T
                + (uint32_t)(lane & 7) * WP_B
                + (uint32_t)(chunk * 128 + kk * 32 + ((lane >> 3) & 1) * 16);
            LDSM2(b0, b1, baddr);
            MMAFP8(la, a, b0, b1);
        }
        __syncthreads();                          // h reads done before next slab0 cp
    }

    // ---- store with mirror (la / 256) ----
    const float invs = 1.f / (WSCALE * WSCALE);
    const int c0 = tig * 2, c1 = c0 + 1;
    const float bias0 = __ldg(b2 + c0);
    const float bias1 = (c1 < NB) ? __ldg(b2 + c1) : 0.f;
    float* ob = out + (size_t)b * NB * NA * NA;
#pragma unroll
    for (int h = 0; h < 2; h++) {
        const int p = wid * 16 + gid + h * 8;
        const int i = iBase + (p >> 4);
        const int j = jBase + (p & 15);
        if (i > j) continue;
        if (i == j) {
            ob[(size_t)c0 * NA * NA + i * NA + j] = MASK_FILL;
            if (c1 < NB) ob[(size_t)c1 * NA * NA + i * NA + j] = MASK_FILL;
            continue;
        }
        const bool valid = (__ldg(mask + b * NA + i) != 0) &&
                           (__ldg(mask + b * NA + j) != 0);
        float v0 = valid ? (la[h * 2 + 0] * invs + bias0) : MASK_FILL;
        ob[(size_t)c0 * NA * NA + i * NA + j] = v0;
        ob[(size_t)c0 * NA * NA + j * NA + i] = v0;
        if (c1 < NB) {
            float v1 = valid ? (la[h * 2 + 1] * invs + bias1) : MASK_FILL;
            ob[(size_t)c1 * NA * NA + i * NA + j] = v1;
            ob[(size_t)c1 * NA * NA + j * NA + i] = v1;
        }
    }
}

extern "C" void kernel_launch(void* const* d_in, const int* in_sizes, int n_in,
                              void* d_out, int out_size) {
    (void)in_sizes; (void)n_in; (void)out_size;
    const float* hs = (const float*)d_in[0];
    const float* W1 = (const float*)d_in[1];
    const float* b1 = (const float*)d_in[2];
    const float* W2 = (const float*)d_in[3];
    const float* b2 = (const float*)d_in[4];
    const int* idx  = (const int*)d_in[5];
    const int* msk  = (const int*)d_in[6];
    float* out = (float*)d_out;

    gather_kernel<<<B_SZ * NA, 128>>>(hs, idx);
    prep2_kernel<<<513, 256>>>(W1, b1, W2);

    cudaFuncSetAttribute(pair_kernel, cudaFuncAttributeMaxDynamicSharedMemorySize, SMEM_REQ);
    pair_kernel<<<dim3(NBLK, 1, B_SZ), 256, SMEM_REQ>>>(b2, msk, out);
}